// round 8
// baseline (speedup 1.0000x reference)
#include <cuda_runtime.h>
#include <math.h>

// Problem dims
#define Bq 64
#define Lq 512
#define Tq 1000
#define Eq 256
#define Hq 512
#define HDq 256
#define Mq 80
#define Sq 128

#define NBLK 128   // persistent grid size (<= 148 SMs, single wave guaranteed)

// ---------------- scratch (__device__ globals; no runtime allocation) ----------------
__device__ float g_xemb[Lq * Bq * Eq];             // [l][b][e]
__device__ float g_projf[Lq * Bq * 4 * HDq];       // [l][b][4Hd]
__device__ float g_projb[Lq * Bq * 4 * HDq];
__device__ float g_encout[(size_t)Bq * Lq * Hq];   // [b][l][H]
__device__ float g_he[2 * 2 * Bq * HDq];           // [dir][parity][b][Hd]
__device__ float g_sp1[Bq * Hq];
__device__ float g_sp[Bq * Hq];
__device__ float g_rnnin[(size_t)Tq * Bq * (Hq + Mq)];   // [t][b][592]
__device__ float g_gp[(size_t)Tq * Bq * 4 * Hq];         // reused layer0 then layer1
__device__ float g_h1[(size_t)Tq * Bq * Hq];
__device__ float g_h2[(size_t)Tq * Bq * Hq];
__device__ float g_melh[(size_t)Tq * Bq * Hq];
__device__ float g_meltmp[(size_t)Tq * Bq * Mq];

__device__ unsigned g_bar_arrive[4];
__device__ unsigned g_bar_gen[4];

__device__ __forceinline__ float sigm(float x) { return 1.f / (1.f + expf(-x)); }

// ---------------- software grid barrier (all blocks resident, single wave) ----------
// Arrival: one atomicAdd per block. Release: atomicExch by last arriver.
// Wait: VOLATILE PLAIN LOAD poll (no L2 atomic-ALU serialization across 128 pollers).
__device__ __forceinline__ void grid_sync(int id, unsigned nb, unsigned gen) {
    __syncthreads();
    if (threadIdx.x == 0) {
        __threadfence();
        unsigned a = atomicAdd(&g_bar_arrive[id], 1u) + 1u;
        if (a == gen * nb) {
            atomicExch(&g_bar_gen[id], gen);
        } else {
            volatile unsigned* p = &g_bar_gen[id];
            while (*p < gen) __nanosleep(64);
        }
        __threadfence();
    }
    __syncthreads();
}

// ---------------- embedding gather ----------------
__global__ void gather_kernel(const int* __restrict__ text, const float* __restrict__ embed,
                              float* __restrict__ xemb) {
    int idx = blockIdx.x * 256 + threadIdx.x;
    if (idx >= Lq * Bq * Eq) return;
    int e = idx & (Eq - 1);
    int lb = idx >> 8;
    int b = lb & (Bq - 1);
    int l = lb >> 6;
    xemb[idx] = embed[text[b * Lq + l] * Eq + e];
}

// ---------------- small-M fp32 GEMM (64x64 tile) for speaker MLP ------------------
__global__ __launch_bounds__(256) void gemm_bias_kernel(
    const float* __restrict__ A, const float* __restrict__ W,
    const float* __restrict__ bias, float* __restrict__ C,
    int M, int N, int K, int relu)
{
    __shared__ float As[16][66];
    __shared__ float Ws[16][66];
    int bm = blockIdx.y * 64;
    int bn = blockIdx.x * 64;
    int tid = threadIdx.x;
    int tx = tid & 15;
    int ty = tid >> 4;
    float acc[4][4];
#pragma unroll
    for (int i = 0; i < 4; i++)
#pragma unroll
        for (int j = 0; j < 4; j++) acc[i][j] = 0.f;

    for (int k0 = 0; k0 < K; k0 += 16) {
#pragma unroll
        for (int i = 0; i < 4; i++) {
            int idx = i * 256 + tid;
            int m = idx >> 4, kk = idx & 15;
            As[kk][m] = (bm + m < M) ? A[(size_t)(bm + m) * K + k0 + kk] : 0.f;
        }
#pragma unroll
        for (int i = 0; i < 4; i++) {
            int idx = i * 256 + tid;
            int n = idx >> 4, kk = idx & 15;
            int gn = bn + n;
            Ws[kk][n] = (gn < N) ? W[(size_t)gn * K + k0 + kk] : 0.f;
        }
        __syncthreads();
#pragma unroll
        for (int kk = 0; kk < 16; kk++) {
            float a0 = As[kk][ty * 4 + 0];
            float a1 = As[kk][ty * 4 + 1];
            float a2 = As[kk][ty * 4 + 2];
            float a3 = As[kk][ty * 4 + 3];
            float w0 = Ws[kk][tx * 4 + 0];
            float w1 = Ws[kk][tx * 4 + 1];
            float w2 = Ws[kk][tx * 4 + 2];
            float w3 = Ws[kk][tx * 4 + 3];
            acc[0][0] += a0 * w0; acc[0][1] += a0 * w1; acc[0][2] += a0 * w2; acc[0][3] += a0 * w3;
            acc[1][0] += a1 * w0; acc[1][1] += a1 * w1; acc[1][2] += a1 * w2; acc[1][3] += a1 * w3;
            acc[2][0] += a2 * w0; acc[2][1] += a2 * w1; acc[2][2] += a2 * w2; acc[2][3] += a2 * w3;
            acc[3][0] += a3 * w0; acc[3][1] += a3 * w1; acc[3][2] += a3 * w2; acc[3][3] += a3 * w3;
        }
        __syncthreads();
    }
#pragma unroll
    for (int i = 0; i < 4; i++) {
        int gm = bm + ty * 4 + i;
        if (gm >= M) continue;
#pragma unroll
        for (int j = 0; j < 4; j++) {
            int gn = bn + tx * 4 + j;
            if (gn < N) {
                float v = acc[i][j] + bias[gn];
                if (relu) v = fmaxf(v, 0.f);
                C[(size_t)gm * N + gn] = v;
            }
        }
    }
}

// ---------------- big fp32 GEMM: 128x64 tile, 8x4 micro, FFMA-bound ---------------
// Requires M % 128 == 0, K % 16 == 0. N arbitrary (guarded).
__global__ __launch_bounds__(256) void gemm_bias_v2(
    const float* __restrict__ A, const float* __restrict__ W,
    const float* __restrict__ bias, float* __restrict__ C,
    int M, int N, int K, int relu)
{
    __shared__ float As[16][132];   // [k][m]
    __shared__ float Ws[16][68];    // [k][n]
    int bm = blockIdx.y * 128;
    int bn = blockIdx.x * 64;
    int tid = threadIdx.x;
    int tx = tid & 15;   // n micro (4 cols)
    int ty = tid >> 4;   // m micro (8 rows)

    float acc[8][4];
#pragma unroll
    for (int i = 0; i < 8; i++)
#pragma unroll
        for (int j = 0; j < 4; j++) acc[i][j] = 0.f;

    // loader roles
    int lam = tid >> 1;            // 0..127  (A row within tile)
    int lak = (tid & 1) * 8;       // 0 or 8  (A k-offset)
    int lwn = tid >> 2;            // 0..63   (W row within tile)
    int lwk = (tid & 3) * 4;       // 0,4,8,12

    const float* Arow = A + (size_t)(bm + lam) * K + lak;
    bool wok = (bn + lwn < N);
    const float* Wrow = wok ? (W + (size_t)(bn + lwn) * K + lwk) : W;

    for (int k0 = 0; k0 < K; k0 += 16) {
        // prefetch from gmem before the barrier (overlaps prior compute)
        float4 a0 = *(const float4*)(Arow + k0);
        float4 a1 = *(const float4*)(Arow + k0 + 4);
        float4 wv = *(const float4*)(Wrow + k0);
        if (!wok) wv = make_float4(0.f, 0.f, 0.f, 0.f);
        __syncthreads();   // prior compute must finish before overwrite
        As[lak + 0][lam] = a0.x; As[lak + 1][lam] = a0.y;
        As[lak + 2][lam] = a0.z; As[lak + 3][lam] = a0.w;
        As[lak + 4][lam] = a1.x; As[lak + 5][lam] = a1.y;
        As[lak + 6][lam] = a1.z; As[lak + 7][lam] = a1.w;
        Ws[lwk + 0][lwn] = wv.x; Ws[lwk + 1][lwn] = wv.y;
        Ws[lwk + 2][lwn] = wv.z; Ws[lwk + 3][lwn] = wv.w;
        __syncthreads();
#pragma unroll
        for (int kk = 0; kk < 16; kk++) {
            float4 av0 = *(const float4*)&As[kk][ty * 8];
            float4 av1 = *(const float4*)&As[kk][ty * 8 + 4];
            float4 wv2 = *(const float4*)&Ws[kk][tx * 4];
            float am[8] = {av0.x, av0.y, av0.z, av0.w, av1.x, av1.y, av1.z, av1.w};
#pragma unroll
            for (int i = 0; i < 8; i++) {
                acc[i][0] += am[i] * wv2.x;
                acc[i][1] += am[i] * wv2.y;
                acc[i][2] += am[i] * wv2.z;
                acc[i][3] += am[i] * wv2.w;
            }
        }
    }
#pragma unroll
    for (int i = 0; i < 8; i++) {
        int gm = bm + ty * 8 + i;
#pragma unroll
        for (int j = 0; j < 4; j++) {
            int gn = bn + tx * 4 + j;
            if (gn < N) {
                float v = acc[i][j] + bias[gn];
                if (relu) v = fmaxf(v, 0.f);
                C[(size_t)gm * N + gn] = v;
            }
        }
    }
}

// ---------------- persistent decoder LSTM layer (H=512, all T steps in one kernel) ----
__global__ __launch_bounds__(128) void dec_lstm_persist(
    const float* __restrict__ gp,   // [T][B][4H] input projection incl. bias
    const float* __restrict__ W,    // [4H][H]
    float* __restrict__ hseq,       // [T][B][H] output (and recurrent input)
    int T, int barid)
{
    const int H = Hq, B = Bq;
    int bid = blockIdx.x;
    int j0 = bid * 4;
    int tid = threadIdx.x;
    int tb = tid & 15, tc = tid >> 4;   // tc 0..7
    int b0 = tb * 4, c0 = tc * 2;

    __shared__ float ws[Hq][16];        // [k][c], c = q*4+jj   (32 KB)
    __shared__ float hs[32][68];        // [kk][b] chunk        (8.5 KB)
    __shared__ float Gs[64][17];        // [b][c]
    __shared__ float cs[4][64];         // [jj][b]

    // load weight slice once
#pragma unroll 4
    for (int it = 0; it < 64; it++) {
        int idx = it * 128 + tid;
        int k = idx & (H - 1);
        int cc = idx >> 9;
        int row = (cc >> 2) * H + j0 + (cc & 3);
        ws[k][cc] = W[(size_t)row * H + k];
    }
    cs[0][tid & 63] = 0.f; cs[1][tid & 63] = 0.f;
    cs[2][tid & 63] = 0.f; cs[3][tid & 63] = 0.f;
    __syncthreads();

    for (int t = 0; t < T; t++) {
        float acc[4][2];
#pragma unroll
        for (int i = 0; i < 4; i++) { acc[i][0] = 0.f; acc[i][1] = 0.f; }

        if (t > 0) {
            const float* hp = hseq + (size_t)(t - 1) * B * H;
            for (int k0 = 0; k0 < H; k0 += 32) {
#pragma unroll
                for (int i = 0; i < 4; i++) {
                    int idx = i * 128 + tid;     // 0..511
                    int b = idx >> 3;
                    int k4 = (idx & 7) * 4;
                    float4 v = *(const float4*)(hp + b * H + k0 + k4);
                    hs[k4 + 0][b] = v.x; hs[k4 + 1][b] = v.y;
                    hs[k4 + 2][b] = v.z; hs[k4 + 3][b] = v.w;
                }
                __syncthreads();
#pragma unroll
                for (int kk = 0; kk < 32; kk++) {
                    float4 a = *(const float4*)&hs[kk][b0];
                    float2 w = *(const float2*)&ws[k0 + kk][c0];
                    acc[0][0] += a.x * w.x; acc[0][1] += a.x * w.y;
                    acc[1][0] += a.y * w.x; acc[1][1] += a.y * w.y;
                    acc[2][0] += a.z * w.x; acc[2][1] += a.z * w.y;
                    acc[3][0] += a.w * w.x; acc[3][1] += a.w * w.y;
                }
                __syncthreads();
            }
        }

        // stage gp into Gs
        const float* gpt = gp + (size_t)t * B * 4 * H;
#pragma unroll
        for (int r = 0; r < 8; r++) {
            int idx = r * 128 + tid;     // 0..1023
            int b = idx >> 4;
            int cc = idx & 15;
            Gs[b][cc] = gpt[b * 4 * H + (cc >> 2) * H + j0 + (cc & 3)];
        }
        __syncthreads();
#pragma unroll
        for (int i = 0; i < 4; i++) {
            Gs[b0 + i][c0 + 0] += acc[i][0];
            Gs[b0 + i][c0 + 1] += acc[i][1];
        }
        __syncthreads();

        // cell update: 256 cells, 2 per thread
        float* ht = hseq + (size_t)t * B * H;
#pragma unroll
        for (int r = 0; r < 2; r++) {
            int p = r * 128 + tid;
            int b = p & 63;
            int jj = p >> 6;
            float gi = Gs[b][jj];
            float gf = Gs[b][4 + jj];
            float gg = Gs[b][8 + jj];
            float go = Gs[b][12 + jj];
            float cv = cs[jj][b];
            float cn = sigm(gf) * cv + sigm(gi) * tanhf(gg);
            float hv = sigm(go) * tanhf(cn);
            cs[jj][b] = cn;
            ht[b * H + j0 + jj] = hv;
        }
        grid_sync(barid, gridDim.x, (unsigned)(t + 1));
    }
}

// ---------------- persistent bidirectional encoder LSTM (Hd=256, both dirs) --------
__global__ __launch_bounds__(128) void enc_lstm_persist(
    const float* __restrict__ gpf, const float* __restrict__ Wf,
    const float* __restrict__ gpb, const float* __restrict__ Wb,
    float* __restrict__ hbuf,       // [dir][parity][B][Hd]
    float* __restrict__ encout,     // [B][L][H]
    int barid)
{
    const int H = HDq, B = Bq, L = Lq;
    int bid = blockIdx.x;
    int dir = bid >> 6;
    int j0 = (bid & 63) * 4;
    int tid = threadIdx.x;
    int tb = tid & 15, tc = tid >> 4;
    int b0 = tb * 4, c0 = tc * 2;

    const float* gp = dir ? gpb : gpf;
    const float* W  = dir ? Wb : Wf;
    float* hping = hbuf + dir * 2 * B * H;

    __shared__ float ws[HDq][16];     // 16 KB
    __shared__ float hs[32][68];
    __shared__ float Gs[64][17];
    __shared__ float cs[4][64];

#pragma unroll 4
    for (int it = 0; it < 32; it++) {
        int idx = it * 128 + tid;
        int k = idx & (H - 1);
        int cc = idx >> 8;
        int row = (cc >> 2) * H + j0 + (cc & 3);
        ws[k][cc] = W[(size_t)row * H + k];
    }
    cs[0][tid & 63] = 0.f; cs[1][tid & 63] = 0.f;
    cs[2][tid & 63] = 0.f; cs[3][tid & 63] = 0.f;
    __syncthreads();

    for (int l = 0; l < L; l++) {
        int pos = dir ? (L - 1 - l) : l;
        float acc[4][2];
#pragma unroll
        for (int i = 0; i < 4; i++) { acc[i][0] = 0.f; acc[i][1] = 0.f; }

        if (l > 0) {
            const float* hp = hping + (l & 1) * B * H;
            for (int k0 = 0; k0 < H; k0 += 32) {
#pragma unroll
                for (int i = 0; i < 4; i++) {
                    int idx = i * 128 + tid;
                    int b = idx >> 3;
                    int k4 = (idx & 7) * 4;
                    float4 v = *(const float4*)(hp + b * H + k0 + k4);
                    hs[k4 + 0][b] = v.x; hs[k4 + 1][b] = v.y;
                    hs[k4 + 2][b] = v.z; hs[k4 + 3][b] = v.w;
                }
                __syncthreads();
#pragma unroll
                for (int kk = 0; kk < 32; kk++) {
                    float4 a = *(const float4*)&hs[kk][b0];
                    float2 w = *(const float2*)&ws[k0 + kk][c0];
                    acc[0][0] += a.x * w.x; acc[0][1] += a.x * w.y;
                    acc[1][0] += a.y * w.x; acc[1][1] += a.y * w.y;
                    acc[2][0] += a.z * w.x; acc[2][1] += a.z * w.y;
                    acc[3][0] += a.w * w.x; acc[3][1] += a.w * w.y;
                }
                __syncthreads();
            }
        }

        const float* gpt = gp + (size_t)pos * B * 4 * H;
#pragma unroll
        for (int r = 0; r < 8; r++) {
            int idx = r * 128 + tid;
            int b = idx >> 4;
            int cc = idx & 15;
            Gs[b][cc] = gpt[b * 4 * H + (cc >> 2) * H + j0 + (cc & 3)];
        }
        __syncthreads();
#pragma unroll
        for (int i = 0; i < 4; i++) {
            Gs[b0 + i][c0 + 0] += acc[i][0];
            Gs[b0 + i][c0 + 1] += acc[i][1];
        }
        __syncthreads();

        float* hn = hping + ((l + 1) & 1) * B * H;
#pragma unroll
        for (int r = 0; r < 2; r++) {
            int p = r * 128 + tid;
            int b = p & 63;
            int jj = p >> 6;
            float gi = Gs[b][jj];
            float gf = Gs[b][4 + jj];
            float gg = Gs[b][8 + jj];
            float go = Gs[b][12 + jj];
            float cv = cs[jj][b];
            float cn = sigm(gf) * cv + sigm(gi) * tanhf(gg);
            float hv = sigm(go) * tanhf(cn);
            cs[jj][b] = cn;
            hn[b * H + j0 + jj] = hv;
            encout[((size_t)b * L + pos) * Hq + dir * HDq + j0 + jj] = hv;
        }
        grid_sync(barid, gridDim.x, (unsigned)(l + 1));
    }
}

// ---------------- small elementwise kernels ----------------
__global__ void addsp_kernel(float* __restrict__ encout, const float* __restrict__ sp) {
    int idx = blockIdx.x * 256 + threadIdx.x;
    if (idx >= Bq * Lq * Hq) return;
    int j = idx & (Hq - 1);
    int b = idx / (Lq * Hq);
    encout[idx] += sp[b * Hq + j];
}

__global__ void build_rnnin_kernel(const float* __restrict__ mel, const float* __restrict__ encout,
                                   float* __restrict__ rnnin) {
    int idx = blockIdx.x * 256 + threadIdx.x;
    const int KI = Hq + Mq;  // 592
    if (idx >= Tq * Bq * KI) return;
    int k = idx % KI;
    int tb = idx / KI;
    int b = tb & (Bq - 1);
    int t = tb >> 6;
    float v;
    if (k < Mq) {
        v = (t == 0) ? 0.f : mel[((size_t)b * Tq + (t - 1)) * Mq + k];
    } else {
        v = encout[((size_t)b * Lq + (t % Lq)) * Hq + (k - Mq)];
    }
    rnnin[idx] = v;
}

__global__ void mel_rearrange_kernel(const float* __restrict__ meltmp, float* __restrict__ out) {
    int idx = blockIdx.x * 256 + threadIdx.x;
    if (idx >= Tq * Bq * Mq) return;
    int m = idx % Mq;
    int tb = idx / Mq;
    int b = tb & (Bq - 1);
    int t = tb >> 6;
    out[((size_t)b * Tq + t) * Mq + m] = meltmp[idx];
}

__global__ void stop_kernel(const float* __restrict__ h2, const float* __restrict__ stW,
                            const float* __restrict__ stb, float* __restrict__ out) {
    int w = (blockIdx.x * 256 + threadIdx.x) >> 5;
    int lane = threadIdx.x & 31;
    if (w >= Tq * Bq) return;
    int b = w & (Bq - 1);
    int t = w >> 6;
    const float* row = h2 + (size_t)w * Hq;
    float s = 0.f;
#pragma unroll
    for (int k = lane; k < Hq; k += 32) s += row[k] * stW[k];
#pragma unroll
    for (int off = 16; off; off >>= 1) s += __shfl_xor_sync(0xffffffffu, s, off);
    if (lane == 0) out[(size_t)b * Tq + t] = s + stb[0];
}

// ---------------- host driver ----------------
static inline float* sym(const void* s) {
    void* p = nullptr;
    cudaGetSymbolAddress(&p, s);
    return (float*)p;
}

extern "C" void kernel_launch(void* const* d_in, const int* in_sizes, int n_in,
                              void* d_out, int out_size) {
    const int*   text  = (const int*)d_in[0];
    const float* spk   = (const float*)d_in[1];
    const float* tmel  = (const float*)d_in[2];
    const float* embed = (const float*)d_in[3];
    const float* eWihf = (const float*)d_in[4];
    const float* eWhhf = (const float*)d_in[5];
    const float* ebf   = (const float*)d_in[6];
    const float* eWihb = (const float*)d_in[7];
    const float* eWhhb = (const float*)d_in[8];
    const float* ebb   = (const float*)d_in[9];
    const float* spW1  = (const float*)d_in[10];
    const float* spb1  = (const float*)d_in[11];
    const float* spW2  = (const float*)d_in[12];
    const float* spb2  = (const float*)d_in[13];
    const float* dWih0 = (const float*)d_in[14];
    const float* dWhh0 = (const float*)d_in[15];
    const float* db0   = (const float*)d_in[16];
    const float* dWih1 = (const float*)d_in[17];
    const float* dWhh1 = (const float*)d_in[18];
    const float* db1   = (const float*)d_in[19];
    const float* mW1   = (const float*)d_in[20];
    const float* mb1   = (const float*)d_in[21];
    const float* mW2   = (const float*)d_in[22];
    const float* mb2   = (const float*)d_in[23];
    const float* stW   = (const float*)d_in[24];
    const float* stb   = (const float*)d_in[25];
    float* out = (float*)d_out;

    float* xemb   = sym(g_xemb);
    float* projf  = sym(g_projf);
    float* projb  = sym(g_projb);
    float* encout = sym(g_encout);
    float* he     = sym(g_he);
    float* sp1    = sym(g_sp1);
    float* sp     = sym(g_sp);
    float* rnnin  = sym(g_rnnin);
    float* gp     = sym(g_gp);
    float* h1     = sym(g_h1);
    float* h2     = sym(g_h2);
    float* melh   = sym(g_melh);
    float* meltmp = sym(g_meltmp);
    void* barA = nullptr; cudaGetSymbolAddress(&barA, g_bar_arrive);
    void* barG = nullptr; cudaGetSymbolAddress(&barG, g_bar_gen);

    // reset barrier state (captured into graph -> reset on every replay)
    cudaMemsetAsync(barA, 0, 4 * sizeof(unsigned), 0);
    cudaMemsetAsync(barG, 0, 4 * sizeof(unsigned), 0);

    // 1) embedding gather
    gather_kernel<<<(Lq * Bq * Eq + 255) / 256, 256>>>(text, embed, xemb);

    // 2) encoder input projections (bias folded in) — M=32768 %128==0
    {
        dim3 g((4 * HDq + 63) / 64, (Lq * Bq) / 128);
        gemm_bias_v2<<<g, 256>>>(xemb, eWihf, ebf, projf, Lq * Bq, 4 * HDq, Eq, 0);
        gemm_bias_v2<<<g, 256>>>(xemb, eWihb, ebb, projb, Lq * Bq, 4 * HDq, Eq, 0);
    }

    // 3) encoder bidirectional recurrence: ONE persistent kernel
    enc_lstm_persist<<<NBLK, 128>>>(projf, eWhhf, projb, eWhhb, he, encout, 0);

    // 4) speaker MLP (M=64 -> guarded 64x64 kernel)
    {
        dim3 g((Hq + 63) / 64, (Bq + 63) / 64);
        gemm_bias_kernel<<<g, 256>>>(spk, spW1, spb1, sp1, Bq, Hq, Sq, 1);
        gemm_bias_kernel<<<g, 256>>>(sp1, spW2, spb2, sp, Bq, Hq, Hq, 0);
    }

    // 5) encoder_output += sp
    addsp_kernel<<<(Bq * Lq * Hq + 255) / 256, 256>>>(encout, sp);

    // 6) build decoder rnn input [t][b][592]
    build_rnnin_kernel<<<(Tq * Bq * (Hq + Mq) + 255) / 256, 256>>>(tmel, encout, rnnin);

    // 7) decoder layer0 input projection — M=64000 %128==0, K=592 %16==0
    {
        dim3 g((4 * Hq + 63) / 64, (Tq * Bq) / 128);
        gemm_bias_v2<<<g, 256>>>(rnnin, dWih0, db0, gp, Tq * Bq, 4 * Hq, Hq + Mq, 0);
    }

    // 8) decoder layer0 recurrence: ONE persistent kernel
    dec_lstm_persist<<<NBLK, 128>>>(gp, dWhh0, h1, Tq, 1);

    // 9) decoder layer1 input projection (reuse gp)
    {
        dim3 g((4 * Hq + 63) / 64, (Tq * Bq) / 128);
        gemm_bias_v2<<<g, 256>>>(h1, dWih1, db1, gp, Tq * Bq, 4 * Hq, Hq, 0);
    }

    // 10) decoder layer1 recurrence
    dec_lstm_persist<<<NBLK, 128>>>(gp, dWhh1, h2, Tq, 2);

    // 11) mel head
    {
        dim3 g1((Hq + 63) / 64, (Tq * Bq) / 128);
        gemm_bias_v2<<<g1, 256>>>(h2, mW1, mb1, melh, Tq * Bq, Hq, Hq, 1);
        dim3 g2((Mq + 63) / 64, (Tq * Bq) / 128);
        gemm_bias_v2<<<g2, 256>>>(melh, mW2, mb2, meltmp, Tq * Bq, Mq, Hq, 0);
    }
    mel_rearrange_kernel<<<(Tq * Bq * Mq + 255) / 256, 256>>>(meltmp, out);

    // 12) stop head
    stop_kernel<<<(Tq * Bq * 32 + 255) / 256, 256>>>(h2, stW, stb, out + (size_t)Bq * Tq * Mq);
}

// round 9
// speedup vs baseline: 1.3987x; 1.3987x over previous
#include <cuda_runtime.h>
#include <math.h>

// Problem dims
#define Bq 64
#define Lq 512
#define Tq 1000
#define Eq 256
#define Hq 512
#define HDq 256
#define Mq 80
#define Sq 128

#define NBLK 128   // persistent grid size (<= 148 SMs, single wave guaranteed)

// ---------------- scratch (__device__ globals; no runtime allocation) ----------------
__device__ float g_xemb[Lq * Bq * Eq];             // [l][b][e]
__device__ float g_projf[Lq * Bq * 4 * HDq];       // [l][b][4Hd]
__device__ float g_projb[Lq * Bq * 4 * HDq];
__device__ float g_encout[(size_t)Bq * Lq * Hq];   // [b][l][H]
__device__ float g_he[2 * 2 * Bq * HDq];           // [dir][parity][b][Hd]
__device__ float g_sp1[Bq * Hq];
__device__ float g_sp[Bq * Hq];
__device__ float g_rnnin[(size_t)Tq * Bq * (Hq + Mq)];   // [t][b][592]
__device__ float g_gp[(size_t)Tq * Bq * 4 * Hq];         // reused layer0 then layer1
__device__ float g_h1[(size_t)Tq * Bq * Hq];
__device__ float g_h2[(size_t)Tq * Bq * Hq];
__device__ float g_melh[(size_t)Tq * Bq * Hq];
__device__ float g_meltmp[(size_t)Tq * Bq * Mq];

__device__ unsigned g_bar_arrive[4];
__device__ unsigned g_bar_gen[4];

__device__ __forceinline__ float sigm(float x) { return 1.f / (1.f + expf(-x)); }

// ---------------- software grid barrier (all blocks resident, single wave) ----------
__device__ __forceinline__ void grid_sync(int id, unsigned nb, unsigned gen) {
    __syncthreads();
    if (threadIdx.x == 0) {
        __threadfence();
        unsigned a = atomicAdd(&g_bar_arrive[id], 1u) + 1u;
        if (a == gen * nb) {
            atomicExch(&g_bar_gen[id], gen);
        } else {
            volatile unsigned* p = &g_bar_gen[id];
            while (*p < gen) __nanosleep(64);
        }
        __threadfence();
    }
    __syncthreads();
}

// ---------------- embedding gather ----------------
__global__ void gather_kernel(const int* __restrict__ text, const float* __restrict__ embed,
                              float* __restrict__ xemb) {
    int idx = blockIdx.x * 256 + threadIdx.x;
    if (idx >= Lq * Bq * Eq) return;
    int e = idx & (Eq - 1);
    int lb = idx >> 8;
    int b = lb & (Bq - 1);
    int l = lb >> 6;
    xemb[idx] = embed[text[b * Lq + l] * Eq + e];
}

// ---------------- small-M fp32 GEMM (64x64 tile) for speaker MLP ------------------
__global__ __launch_bounds__(256) void gemm_bias_kernel(
    const float* __restrict__ A, const float* __restrict__ W,
    const float* __restrict__ bias, float* __restrict__ C,
    int M, int N, int K, int relu)
{
    __shared__ float As[16][66];
    __shared__ float Ws[16][66];
    int bm = blockIdx.y * 64;
    int bn = blockIdx.x * 64;
    int tid = threadIdx.x;
    int tx = tid & 15;
    int ty = tid >> 4;
    float acc[4][4];
#pragma unroll
    for (int i = 0; i < 4; i++)
#pragma unroll
        for (int j = 0; j < 4; j++) acc[i][j] = 0.f;

    for (int k0 = 0; k0 < K; k0 += 16) {
#pragma unroll
        for (int i = 0; i < 4; i++) {
            int idx = i * 256 + tid;
            int m = idx >> 4, kk = idx & 15;
            As[kk][m] = (bm + m < M) ? A[(size_t)(bm + m) * K + k0 + kk] : 0.f;
        }
#pragma unroll
        for (int i = 0; i < 4; i++) {
            int idx = i * 256 + tid;
            int n = idx >> 4, kk = idx & 15;
            int gn = bn + n;
            Ws[kk][n] = (gn < N) ? W[(size_t)gn * K + k0 + kk] : 0.f;
        }
        __syncthreads();
#pragma unroll
        for (int kk = 0; kk < 16; kk++) {
            float a0 = As[kk][ty * 4 + 0];
            float a1 = As[kk][ty * 4 + 1];
            float a2 = As[kk][ty * 4 + 2];
            float a3 = As[kk][ty * 4 + 3];
            float w0 = Ws[kk][tx * 4 + 0];
            float w1 = Ws[kk][tx * 4 + 1];
            float w2 = Ws[kk][tx * 4 + 2];
            float w3 = Ws[kk][tx * 4 + 3];
            acc[0][0] += a0 * w0; acc[0][1] += a0 * w1; acc[0][2] += a0 * w2; acc[0][3] += a0 * w3;
            acc[1][0] += a1 * w0; acc[1][1] += a1 * w1; acc[1][2] += a1 * w2; acc[1][3] += a1 * w3;
            acc[2][0] += a2 * w0; acc[2][1] += a2 * w1; acc[2][2] += a2 * w2; acc[2][3] += a2 * w3;
            acc[3][0] += a3 * w0; acc[3][1] += a3 * w1; acc[3][2] += a3 * w2; acc[3][3] += a3 * w3;
        }
        __syncthreads();
    }
#pragma unroll
    for (int i = 0; i < 4; i++) {
        int gm = bm + ty * 4 + i;
        if (gm >= M) continue;
#pragma unroll
        for (int j = 0; j < 4; j++) {
            int gn = bn + tx * 4 + j;
            if (gn < N) {
                float v = acc[i][j] + bias[gn];
                if (relu) v = fmaxf(v, 0.f);
                C[(size_t)gm * N + gn] = v;
            }
        }
    }
}

// ---------------- big fp32 GEMM: 128x64 tile, 8x4 micro, FFMA-bound ---------------
__global__ __launch_bounds__(256) void gemm_bias_v2(
    const float* __restrict__ A, const float* __restrict__ W,
    const float* __restrict__ bias, float* __restrict__ C,
    int M, int N, int K, int relu)
{
    __shared__ float As[16][132];   // [k][m]
    __shared__ float Ws[16][68];    // [k][n]
    int bm = blockIdx.y * 128;
    int bn = blockIdx.x * 64;
    int tid = threadIdx.x;
    int tx = tid & 15;   // n micro (4 cols)
    int ty = tid >> 4;   // m micro (8 rows)

    float acc[8][4];
#pragma unroll
    for (int i = 0; i < 8; i++)
#pragma unroll
        for (int j = 0; j < 4; j++) acc[i][j] = 0.f;

    int lam = tid >> 1;            // 0..127  (A row within tile)
    int lak = (tid & 1) * 8;       // 0 or 8  (A k-offset)
    int lwn = tid >> 2;            // 0..63   (W row within tile)
    int lwk = (tid & 3) * 4;       // 0,4,8,12

    const float* Arow = A + (size_t)(bm + lam) * K + lak;
    bool wok = (bn + lwn < N);
    const float* Wrow = wok ? (W + (size_t)(bn + lwn) * K + lwk) : W;

    for (int k0 = 0; k0 < K; k0 += 16) {
        float4 a0 = *(const float4*)(Arow + k0);
        float4 a1 = *(const float4*)(Arow + k0 + 4);
        float4 wv = *(const float4*)(Wrow + k0);
        if (!wok) wv = make_float4(0.f, 0.f, 0.f, 0.f);
        __syncthreads();
        As[lak + 0][lam] = a0.x; As[lak + 1][lam] = a0.y;
        As[lak + 2][lam] = a0.z; As[lak + 3][lam] = a0.w;
        As[lak + 4][lam] = a1.x; As[lak + 5][lam] = a1.y;
        As[lak + 6][lam] = a1.z; As[lak + 7][lam] = a1.w;
        Ws[lwk + 0][lwn] = wv.x; Ws[lwk + 1][lwn] = wv.y;
        Ws[lwk + 2][lwn] = wv.z; Ws[lwk + 3][lwn] = wv.w;
        __syncthreads();
#pragma unroll
        for (int kk = 0; kk < 16; kk++) {
            float4 av0 = *(const float4*)&As[kk][ty * 8];
            float4 av1 = *(const float4*)&As[kk][ty * 8 + 4];
            float4 wv2 = *(const float4*)&Ws[kk][tx * 4];
            float am[8] = {av0.x, av0.y, av0.z, av0.w, av1.x, av1.y, av1.z, av1.w};
#pragma unroll
            for (int i = 0; i < 8; i++) {
                acc[i][0] += am[i] * wv2.x;
                acc[i][1] += am[i] * wv2.y;
                acc[i][2] += am[i] * wv2.z;
                acc[i][3] += am[i] * wv2.w;
            }
        }
    }
#pragma unroll
    for (int i = 0; i < 8; i++) {
        int gm = bm + ty * 8 + i;
#pragma unroll
        for (int j = 0; j < 4; j++) {
            int gn = bn + tx * 4 + j;
            if (gn < N) {
                float v = acc[i][j] + bias[gn];
                if (relu) v = fmaxf(v, 0.f);
                C[(size_t)gm * N + gn] = v;
            }
        }
    }
}

// ---------------- persistent decoder LSTM v2: 256 thr, K-split, double-buffered ----
// Dynamic smem layout (floats): ws[512*16] | hs[64*68] | Gs[64*17] | Ps[64*17]
#define DEC_SMEM_FLOATS (512*16 + 64*68 + 64*17 + 64*17)
#define DEC_SMEM_BYTES  (DEC_SMEM_FLOATS * 4)

__global__ __launch_bounds__(256) void dec_lstm_persist(
    const float* __restrict__ gp,   // [T][B][4H] input projection incl. bias
    const float* __restrict__ W,    // [4H][H]
    float* __restrict__ hseq,       // [T][B][H]
    int T, int barid)
{
    extern __shared__ float smem[];
    float* ws = smem;                       // [k][16]
    float* hs = smem + 512 * 16;            // [64 rows][68]
    float* Gs = hs + 64 * 68;               // [64][17]
    float* Ps = Gs + 64 * 17;               // [64][17]

    const int H = Hq, B = Bq;
    int bid = blockIdx.x;
    int j0 = bid * 4;
    int tid = threadIdx.x;
    int half = tid >> 7;                    // K-split half
    int wtid = tid & 127;
    int tb = wtid & 15, tc = wtid >> 4;
    int b0 = tb * 4, c0 = tc * 2;
    int kbase = half * 256;

    // weight slice load once: 8192 floats
#pragma unroll 4
    for (int it = 0; it < 32; it++) {
        int idx = it * 256 + tid;
        int k = idx & 511;
        int cc = idx >> 9;
        int row = (cc >> 2) * H + j0 + (cc & 3);
        ws[k * 16 + cc] = W[(size_t)row * H + k];
    }
    // per-thread h loader coords (within this half's 32-row chunk region)
    int lb[4], lk[4];
#pragma unroll
    for (int i = 0; i < 4; i++) {
        int idx = i * 128 + wtid;
        lb[i] = idx >> 3;
        lk[i] = (idx & 7) * 4;
    }
    // this thread's cell (constant across steps) -> c state in register
    int cb = tid >> 2, cj = tid & 3;
    float creg = 0.f;
    __syncthreads();

    for (int t = 0; t < T; t++) {
        float acc[4][2];
#pragma unroll
        for (int i = 0; i < 4; i++) { acc[i][0] = 0.f; acc[i][1] = 0.f; }

        if (t > 0) {
            const float* hp = hseq + (size_t)(t - 1) * B * H;
            float4 pv[4];
#pragma unroll
            for (int i = 0; i < 4; i++)
                pv[i] = *(const float4*)(hp + lb[i] * H + kbase + lk[i]);
            for (int c = 0; c < 8; c++) {
                __syncthreads();            // prior chunk compute done -> hs free
#pragma unroll
                for (int i = 0; i < 4; i++) {
                    int r = half * 32 + lk[i];
                    hs[(r + 0) * 68 + lb[i]] = pv[i].x;
                    hs[(r + 1) * 68 + lb[i]] = pv[i].y;
                    hs[(r + 2) * 68 + lb[i]] = pv[i].z;
                    hs[(r + 3) * 68 + lb[i]] = pv[i].w;
                }
                if (c < 7) {                // prefetch next chunk (overlaps compute)
#pragma unroll
                    for (int i = 0; i < 4; i++)
                        pv[i] = *(const float4*)(hp + lb[i] * H + kbase + (c + 1) * 32 + lk[i]);
                }
                __syncthreads();
                int k0 = kbase + c * 32;
#pragma unroll
                for (int kk = 0; kk < 32; kk++) {
                    float4 a = *(const float4*)&hs[(half * 32 + kk) * 68 + b0];
                    float2 w = *(const float2*)&ws[(k0 + kk) * 16 + c0];
                    acc[0][0] += a.x * w.x; acc[0][1] += a.x * w.y;
                    acc[1][0] += a.y * w.x; acc[1][1] += a.y * w.y;
                    acc[2][0] += a.z * w.x; acc[2][1] += a.z * w.y;
                    acc[3][0] += a.w * w.x; acc[3][1] += a.w * w.y;
                }
            }
        }

        // stage gp into Gs (all 256 threads, 4 each)
        __syncthreads();
        const float* gpt = gp + (size_t)t * B * 4 * H;
#pragma unroll
        for (int r = 0; r < 4; r++) {
            int idx = r * 256 + tid;        // 0..1023
            int b = idx >> 4, cc = idx & 15;
            Gs[b * 17 + cc] = gpt[b * 4 * H + (cc >> 2) * H + j0 + (cc & 3)];
        }
        __syncthreads();
        if (half == 0) {
#pragma unroll
            for (int i = 0; i < 4; i++) {
                Gs[(b0 + i) * 17 + c0 + 0] += acc[i][0];
                Gs[(b0 + i) * 17 + c0 + 1] += acc[i][1];
            }
        } else {
#pragma unroll
            for (int i = 0; i < 4; i++) {
                Ps[(b0 + i) * 17 + c0 + 0] = acc[i][0];
                Ps[(b0 + i) * 17 + c0 + 1] = acc[i][1];
            }
        }
        __syncthreads();

        // cell update: exactly one cell per thread
        {
            float gi = Gs[cb * 17 + cj]      + Ps[cb * 17 + cj];
            float gf = Gs[cb * 17 + 4 + cj]  + Ps[cb * 17 + 4 + cj];
            float gg = Gs[cb * 17 + 8 + cj]  + Ps[cb * 17 + 8 + cj];
            float go = Gs[cb * 17 + 12 + cj] + Ps[cb * 17 + 12 + cj];
            creg = sigm(gf) * creg + sigm(gi) * tanhf(gg);
            float hv = sigm(go) * tanhf(creg);
            hseq[(size_t)t * B * H + cb * H + j0 + cj] = hv;
        }
        grid_sync(barid, gridDim.x, (unsigned)(t + 1));
    }
}

// ---------------- persistent bidirectional encoder LSTM v2 (Hd=256) ---------------
// 128 blocks (0..63 fwd, 64..127 bwd) x 256 threads, K-split 2x128.
__global__ __launch_bounds__(256) void enc_lstm_persist(
    const float* __restrict__ gpf, const float* __restrict__ Wf,
    const float* __restrict__ gpb, const float* __restrict__ Wb,
    float* __restrict__ hbuf,       // [dir][parity][B][Hd]
    float* __restrict__ encout,     // [B][L][H]
    int barid)
{
    const int H = HDq, B = Bq, L = Lq;
    int bid = blockIdx.x;
    int dir = bid >> 6;
    int j0 = (bid & 63) * 4;
    int tid = threadIdx.x;
    int half = tid >> 7;
    int wtid = tid & 127;
    int tb = wtid & 15, tc = wtid >> 4;
    int b0 = tb * 4, c0 = tc * 2;
    int kbase = half * 128;

    const float* gp = dir ? gpb : gpf;
    const float* W  = dir ? Wb : Wf;
    float* hping = hbuf + dir * 2 * B * H;

    __shared__ float ws[256 * 16];   // 16 KB
    __shared__ float hs[64 * 68];    // 17 KB
    __shared__ float Gs[64 * 17];
    __shared__ float Ps[64 * 17];

#pragma unroll 4
    for (int it = 0; it < 16; it++) {
        int idx = it * 256 + tid;
        int k = idx & 255;
        int cc = idx >> 8;
        int row = (cc >> 2) * H + j0 + (cc & 3);
        ws[k * 16 + cc] = W[(size_t)row * H + k];
    }
    int lb[4], lk[4];
#pragma unroll
    for (int i = 0; i < 4; i++) {
        int idx = i * 128 + wtid;
        lb[i] = idx >> 3;
        lk[i] = (idx & 7) * 4;
    }
    int cb = tid >> 2, cj = tid & 3;
    float creg = 0.f;
    __syncthreads();

    for (int l = 0; l < L; l++) {
        int pos = dir ? (L - 1 - l) : l;
        float acc[4][2];
#pragma unroll
        for (int i = 0; i < 4; i++) { acc[i][0] = 0.f; acc[i][1] = 0.f; }

        if (l > 0) {
            const float* hp = hping + (l & 1) * B * H;
            float4 pv[4];
#pragma unroll
            for (int i = 0; i < 4; i++)
                pv[i] = *(const float4*)(hp + lb[i] * H + kbase + lk[i]);
            for (int c = 0; c < 4; c++) {
                __syncthreads();
#pragma unroll
                for (int i = 0; i < 4; i++) {
                    int r = half * 32 + lk[i];
                    hs[(r + 0) * 68 + lb[i]] = pv[i].x;
                    hs[(r + 1) * 68 + lb[i]] = pv[i].y;
                    hs[(r + 2) * 68 + lb[i]] = pv[i].z;
                    hs[(r + 3) * 68 + lb[i]] = pv[i].w;
                }
                if (c < 3) {
#pragma unroll
                    for (int i = 0; i < 4; i++)
                        pv[i] = *(const float4*)(hp + lb[i] * H + kbase + (c + 1) * 32 + lk[i]);
                }
                __syncthreads();
                int k0 = kbase + c * 32;
#pragma unroll
                for (int kk = 0; kk < 32; kk++) {
                    float4 a = *(const float4*)&hs[(half * 32 + kk) * 68 + b0];
                    float2 w = *(const float2*)&ws[(k0 + kk) * 16 + c0];
                    acc[0][0] += a.x * w.x; acc[0][1] += a.x * w.y;
                    acc[1][0] += a.y * w.x; acc[1][1] += a.y * w.y;
                    acc[2][0] += a.z * w.x; acc[2][1] += a.z * w.y;
                    acc[3][0] += a.w * w.x; acc[3][1] += a.w * w.y;
                }
            }
        }

        __syncthreads();
        const float* gpt = gp + (size_t)pos * B * 4 * H;
#pragma unroll
        for (int r = 0; r < 4; r++) {
            int idx = r * 256 + tid;
            int b = idx >> 4, cc = idx & 15;
            Gs[b * 17 + cc] = gpt[b * 4 * H + (cc >> 2) * H + j0 + (cc & 3)];
        }
        __syncthreads();
        if (half == 0) {
#pragma unroll
            for (int i = 0; i < 4; i++) {
                Gs[(b0 + i) * 17 + c0 + 0] += acc[i][0];
                Gs[(b0 + i) * 17 + c0 + 1] += acc[i][1];
            }
        } else {
#pragma unroll
            for (int i = 0; i < 4; i++) {
                Ps[(b0 + i) * 17 + c0 + 0] = acc[i][0];
                Ps[(b0 + i) * 17 + c0 + 1] = acc[i][1];
            }
        }
        __syncthreads();

        {
            float gi = Gs[cb * 17 + cj]      + Ps[cb * 17 + cj];
            float gf = Gs[cb * 17 + 4 + cj]  + Ps[cb * 17 + 4 + cj];
            float gg = Gs[cb * 17 + 8 + cj]  + Ps[cb * 17 + 8 + cj];
            float go = Gs[cb * 17 + 12 + cj] + Ps[cb * 17 + 12 + cj];
            creg = sigm(gf) * creg + sigm(gi) * tanhf(gg);
            float hv = sigm(go) * tanhf(creg);
            hping[((l + 1) & 1) * B * H + cb * H + j0 + cj] = hv;
            encout[((size_t)cb * L + pos) * Hq + dir * HDq + j0 + cj] = hv;
        }
        grid_sync(barid, gridDim.x, (unsigned)(l + 1));
    }
}

// ---------------- small elementwise kernels ----------------
__global__ void addsp_kernel(float* __restrict__ encout, const float* __restrict__ sp) {
    int idx = blockIdx.x * 256 + threadIdx.x;
    if (idx >= Bq * Lq * Hq) return;
    int j = idx & (Hq - 1);
    int b = idx / (Lq * Hq);
    encout[idx] += sp[b * Hq + j];
}

__global__ void build_rnnin_kernel(const float* __restrict__ mel, const float* __restrict__ encout,
                                   float* __restrict__ rnnin) {
    int idx = blockIdx.x * 256 + threadIdx.x;
    const int KI = Hq + Mq;  // 592
    if (idx >= Tq * Bq * KI) return;
    int k = idx % KI;
    int tb = idx / KI;
    int b = tb & (Bq - 1);
    int t = tb >> 6;
    float v;
    if (k < Mq) {
        v = (t == 0) ? 0.f : mel[((size_t)b * Tq + (t - 1)) * Mq + k];
    } else {
        v = encout[((size_t)b * Lq + (t % Lq)) * Hq + (k - Mq)];
    }
    rnnin[idx] = v;
}

__global__ void mel_rearrange_kernel(const float* __restrict__ meltmp, float* __restrict__ out) {
    int idx = blockIdx.x * 256 + threadIdx.x;
    if (idx >= Tq * Bq * Mq) return;
    int m = idx % Mq;
    int tb = idx / Mq;
    int b = tb & (Bq - 1);
    int t = tb >> 6;
    out[((size_t)b * Tq + t) * Mq + m] = meltmp[idx];
}

__global__ void stop_kernel(const float* __restrict__ h2, const float* __restrict__ stW,
                            const float* __restrict__ stb, float* __restrict__ out) {
    int w = (blockIdx.x * 256 + threadIdx.x) >> 5;
    int lane = threadIdx.x & 31;
    if (w >= Tq * Bq) return;
    int b = w & (Bq - 1);
    int t = w >> 6;
    const float* row = h2 + (size_t)w * Hq;
    float s = 0.f;
#pragma unroll
    for (int k = lane; k < Hq; k += 32) s += row[k] * stW[k];
#pragma unroll
    for (int off = 16; off; off >>= 1) s += __shfl_xor_sync(0xffffffffu, s, off);
    if (lane == 0) out[(size_t)b * Tq + t] = s + stb[0];
}

// ---------------- host driver ----------------
static inline float* sym(const void* s) {
    void* p = nullptr;
    cudaGetSymbolAddress(&p, s);
    return (float*)p;
}

extern "C" void kernel_launch(void* const* d_in, const int* in_sizes, int n_in,
                              void* d_out, int out_size) {
    const int*   text  = (const int*)d_in[0];
    const float* spk   = (const float*)d_in[1];
    const float* tmel  = (const float*)d_in[2];
    const float* embed = (const float*)d_in[3];
    const float* eWihf = (const float*)d_in[4];
    const float* eWhhf = (const float*)d_in[5];
    const float* ebf   = (const float*)d_in[6];
    const float* eWihb = (const float*)d_in[7];
    const float* eWhhb = (const float*)d_in[8];
    const float* ebb   = (const float*)d_in[9];
    const float* spW1  = (const float*)d_in[10];
    const float* spb1  = (const float*)d_in[11];
    const float* spW2  = (const float*)d_in[12];
    const float* spb2  = (const float*)d_in[13];
    const float* dWih0 = (const float*)d_in[14];
    const float* dWhh0 = (const float*)d_in[15];
    const float* db0   = (const float*)d_in[16];
    const float* dWih1 = (const float*)d_in[17];
    const float* dWhh1 = (const float*)d_in[18];
    const float* db1   = (const float*)d_in[19];
    const float* mW1   = (const float*)d_in[20];
    const float* mb1   = (const float*)d_in[21];
    const float* mW2   = (const float*)d_in[22];
    const float* mb2   = (const float*)d_in[23];
    const float* stW   = (const float*)d_in[24];
    const float* stb   = (const float*)d_in[25];
    float* out = (float*)d_out;

    float* xemb   = sym(g_xemb);
    float* projf  = sym(g_projf);
    float* projb  = sym(g_projb);
    float* encout = sym(g_encout);
    float* he     = sym(g_he);
    float* sp1    = sym(g_sp1);
    float* sp     = sym(g_sp);
    float* rnnin  = sym(g_rnnin);
    float* gp     = sym(g_gp);
    float* h1     = sym(g_h1);
    float* h2     = sym(g_h2);
    float* melh   = sym(g_melh);
    float* meltmp = sym(g_meltmp);
    void* barA = nullptr; cudaGetSymbolAddress(&barA, g_bar_arrive);
    void* barG = nullptr; cudaGetSymbolAddress(&barG, g_bar_gen);

    // dec kernel needs >48KB dynamic smem (idempotent; not a stream op)
    cudaFuncSetAttribute(dec_lstm_persist, cudaFuncAttributeMaxDynamicSharedMemorySize,
                         DEC_SMEM_BYTES);

    // reset barrier state (captured into graph -> reset on every replay)
    cudaMemsetAsync(barA, 0, 4 * sizeof(unsigned), 0);
    cudaMemsetAsync(barG, 0, 4 * sizeof(unsigned), 0);

    // 1) embedding gather
    gather_kernel<<<(Lq * Bq * Eq + 255) / 256, 256>>>(text, embed, xemb);

    // 2) encoder input projections (bias folded in) — M=32768 %128==0
    {
        dim3 g((4 * HDq + 63) / 64, (Lq * Bq) / 128);
        gemm_bias_v2<<<g, 256>>>(xemb, eWihf, ebf, projf, Lq * Bq, 4 * HDq, Eq, 0);
        gemm_bias_v2<<<g, 256>>>(xemb, eWihb, ebb, projb, Lq * Bq, 4 * HDq, Eq, 0);
    }

    // 3) encoder bidirectional recurrence: ONE persistent kernel
    enc_lstm_persist<<<NBLK, 256>>>(projf, eWhhf, projb, eWhhb, he, encout, 0);

    // 4) speaker MLP (M=64 -> guarded 64x64 kernel)
    {
        dim3 g((Hq + 63) / 64, (Bq + 63) / 64);
        gemm_bias_kernel<<<g, 256>>>(spk, spW1, spb1, sp1, Bq, Hq, Sq, 1);
        gemm_bias_kernel<<<g, 256>>>(sp1, spW2, spb2, sp, Bq, Hq, Hq, 0);
    }

    // 5) encoder_output += sp
    addsp_kernel<<<(Bq * Lq * Hq + 255) / 256, 256>>>(encout, sp);

    // 6) build decoder rnn input [t][b][592]
    build_rnnin_kernel<<<(Tq * Bq * (Hq + Mq) + 255) / 256, 256>>>(tmel, encout, rnnin);

    // 7) decoder layer0 input projection — M=64000 %128==0, K=592 %16==0
    {
        dim3 g((4 * Hq + 63) / 64, (Tq * Bq) / 128);
        gemm_bias_v2<<<g, 256>>>(rnnin, dWih0, db0, gp, Tq * Bq, 4 * Hq, Hq + Mq, 0);
    }

    // 8) decoder layer0 recurrence: ONE persistent kernel
    dec_lstm_persist<<<NBLK, 256, DEC_SMEM_BYTES>>>(gp, dWhh0, h1, Tq, 1);

    // 9) decoder layer1 input projection (reuse gp)
    {
        dim3 g((4 * Hq + 63) / 64, (Tq * Bq) / 128);
        gemm_bias_v2<<<g, 256>>>(h1, dWih1, db1, gp, Tq * Bq, 4 * Hq, Hq, 0);
    }

    // 10) decoder layer1 recurrence
    dec_lstm_persist<<<NBLK, 256, DEC_SMEM_BYTES>>>(gp, dWhh1, h2, Tq, 2);

    // 11) mel head
    {
        dim3 g1((Hq + 63) / 64, (Tq * Bq) / 128);
        gemm_bias_v2<<<g1, 256>>>(h2, mW1, mb1, melh, Tq * Bq, Hq, Hq, 1);
        dim3 g2((Mq + 63) / 64, (Tq * Bq) / 128);
        gemm_bias_v2<<<g2, 256>>>(melh, mW2, mb2, meltmp, Tq * Bq, Mq, Hq, 0);
    }
    mel_rearrange_kernel<<<(Tq * Bq * Mq + 255) / 256, 256>>>(meltmp, out);

    // 12) stop head
    stop_kernel<<<(Tq * Bq * 32 + 255) / 256, 256>>>(h2, stW, stb, out + (size_t)Bq * Tq * Mq);
}